// round 3
// baseline (speedup 1.0000x reference)
#include <cuda_runtime.h>

// ThreeBodyLayer — round 3: float4-batched broadcasts + cp.async row prefetch.
//
// Factorized layer 1: cp = core@W1c + b1, A_k = lig_k@W1a, B_k = lig_k@W1b,
// CA_k = cp + A_k.  Per ordered pair (i,j): h1 = sp(CA_i + B_j);
// t = h1@W2 + b2; y += sp(t)·W3[m].  out = 0.5·Σy + 15·b3.
//
// Warp owns a row. 64-dim vectors packed as f32x2 {v[lane], v[lane+32]}.
// All x broadcasts are float4 broadcast-LDS from an SMEM-staged x row that is
// double-buffered and prefetched with cp.async one row ahead. Lig-projection
// weights: one quad = 4 lane-dist LDS.128 feeding 48 packed FMAs (6 ligands).
// W2 columns live in registers (32 ull per lane). All GEMV math fma.rn.f32x2.

typedef unsigned long long ull;

#define FULLMASK 0xFFFFFFFFu

__device__ __forceinline__ ull pk(float lo, float hi) {
    ull r; asm("mov.b64 %0, {%1, %2};" : "=l"(r) : "f"(lo), "f"(hi)); return r;
}
__device__ __forceinline__ void upk(ull v, float& lo, float& hi) {
    asm("mov.b64 {%0, %1}, %2;" : "=f"(lo), "=f"(hi) : "l"(v));
}
__device__ __forceinline__ ull fma2(ull a, ull b, ull c) {
    ull d; asm("fma.rn.f32x2 %0, %1, %2, %3;" : "=l"(d) : "l"(a), "l"(b), "l"(c)); return d;
}
__device__ __forceinline__ ull add2(ull a, ull b) {
    ull d; asm("add.rn.f32x2 %0, %1, %2;" : "=l"(d) : "l"(a), "l"(b)); return d;
}
__device__ __forceinline__ float softplus_f(float x) {
    return fmaxf(x, 0.0f) + __logf(1.0f + __expf(-fabsf(x)));
}
__device__ __forceinline__ void cp_async16(unsigned dst, const void* src) {
    asm volatile("cp.async.cg.shared.global [%0], [%1], 16;" :: "r"(dst), "l"(src));
}

// ---- dynamic SMEM layout ----
// [0,      16384)  ulonglong2 s_wc[32*32]   core-proj weights, 2 packed pairs each
// [16384,  49152)  ulonglong2 s_ab[64*32]   {wa_pack, wb_pack} per (d,lane)
// [49152,  78848)  float      s_x [8][2][464]  double-buffered x row per warp
// [78848,  87040)  float      s_h1[8][256]     h1 double buffer per warp
static constexpr int SMEM_BYTES = 87040;

__global__ void __launch_bounds__(256, 2) three_body_kernel(
    const float* __restrict__ core,   // [B, 64]
    const float* __restrict__ ligs,   // [B, 6, 64]
    const float* __restrict__ W1,     // [192, 64]
    const float* __restrict__ b1,     // [64]
    const float* __restrict__ W2,     // [64, 32]
    const float* __restrict__ b2,     // [32]
    const float* __restrict__ W3,     // [32]
    const float* __restrict__ b3,     // [1]
    float* __restrict__ out,          // [B]
    int B)
{
    extern __shared__ unsigned char sm[];
    ulonglong2* s_wc = reinterpret_cast<ulonglong2*>(sm);
    ulonglong2* s_ab = reinterpret_cast<ulonglong2*>(sm + 16384);
    float*      s_x  = reinterpret_cast<float*>(sm + 49152);
    float*      s_h1 = reinterpret_cast<float*>(sm + 78848);

    // ---- stage weights (block-wide, once) ----
    for (int idx = threadIdx.x; idx < 1024; idx += 256) {
        int tp = idx >> 5, l = idx & 31;       // tp: 0..31, covers W1c rows 2tp, 2tp+1
        ulonglong2 v;
        v.x = pk(W1[(2 * tp)     * 64 + l], W1[(2 * tp)     * 64 + l + 32]);
        v.y = pk(W1[(2 * tp + 1) * 64 + l], W1[(2 * tp + 1) * 64 + l + 32]);
        s_wc[idx] = v;
    }
    for (int idx = threadIdx.x; idx < 2048; idx += 256) {
        int d = idx >> 5, l = idx & 31;
        ulonglong2 v;
        v.x = pk(W1[(64  + d) * 64 + l], W1[(64  + d) * 64 + l + 32]);
        v.y = pk(W1[(128 + d) * 64 + l], W1[(128 + d) * 64 + l + 32]);
        s_ab[idx] = v;
    }
    __syncthreads();

    const int lane = threadIdx.x & 31;
    const int warp = threadIdx.x >> 5;
    const int gw   = (blockIdx.x * 256 + threadIdx.x) >> 5;
    const int nw   = (gridDim.x * 256) >> 5;

    // ---- W2 column for lane m, packed over d-pairs (persistent registers) ----
    ull w2q[32];
    #pragma unroll
    for (int dp = 0; dp < 32; dp++)
        w2q[dp] = pk(W2[(2 * dp) * 32 + lane], W2[(2 * dp + 1) * 32 + lane]);

    const float b1a = b1[lane];
    const float b1b = b1[lane + 32];
    const float b2l = b2[lane];
    const float w3l = W3[lane];
    const float b3v = b3[0];

    float* xw = s_x  + warp * 928;   // two 464-float buffers
    float* hw = s_h1 + warp * 256;   // two 128-float h1 buffers

    // ---- prefetch first row ----
    if (gw < B) {
        unsigned dst = (unsigned)__cvta_generic_to_shared(xw);
        const float4* c4 = reinterpret_cast<const float4*>(core + (size_t)gw * 64);
        const float4* l4 = reinterpret_cast<const float4*>(ligs + (size_t)gw * 384);
        if (lane < 16) cp_async16(dst + lane * 16, c4 + lane);
        #pragma unroll
        for (int t = 0; t < 3; t++)
            cp_async16(dst + (16 + t * 32 + lane) * 16, l4 + t * 32 + lane);
    }
    asm volatile("cp.async.commit_group;");

    int parity = 0;
    for (int r = gw; r < B; r += nw) {
        // ---- prefetch next row into the other buffer ----
        {
            int nr = r + nw;
            if (nr < B) {
                unsigned dst = (unsigned)__cvta_generic_to_shared(xw + (parity ^ 1) * 464);
                const float4* c4 = reinterpret_cast<const float4*>(core + (size_t)nr * 64);
                const float4* l4 = reinterpret_cast<const float4*>(ligs + (size_t)nr * 384);
                if (lane < 16) cp_async16(dst + lane * 16, c4 + lane);
                #pragma unroll
                for (int t = 0; t < 3; t++)
                    cp_async16(dst + (16 + t * 32 + lane) * 16, l4 + t * 32 + lane);
            }
            asm volatile("cp.async.commit_group;");
            asm volatile("cp.async.wait_group 1;");   // current row's group done
            __syncwarp();
        }
        const float* xc = xw + parity * 464;
        parity ^= 1;

        // ---- core projection: cp = core@W1c + b1 (packed halves) ----
        ull cpA = pk(b1a, b1b), cpB = pk(0.0f, 0.0f);
        {
            const float4* x4 = reinterpret_cast<const float4*>(xc);
            #pragma unroll
            for (int t = 0; t < 16; t++) {
                float4 q = x4[t];                          // broadcast LDS.128
                ulonglong2 w0 = s_wc[(2 * t)     * 32 + lane];
                ulonglong2 w1 = s_wc[(2 * t + 1) * 32 + lane];
                cpA = fma2(pk(q.x, q.x), w0.x, cpA);
                cpB = fma2(pk(q.y, q.y), w0.y, cpB);
                cpA = fma2(pk(q.z, q.z), w1.x, cpA);
                cpB = fma2(pk(q.w, q.w), w1.y, cpB);
            }
        }
        const ull cp = add2(cpA, cpB);

        // ---- lig projections: one d-quad of weights feeds all 6 ligands ----
        ull accA[6], accB[6];
        #pragma unroll
        for (int k = 0; k < 6; k++) { accA[k] = pk(0.f, 0.f); accB[k] = pk(0.f, 0.f); }
        {
            const float4* xl4 = reinterpret_cast<const float4*>(xc + 64);
            #pragma unroll 4
            for (int t = 0; t < 16; t++) {
                ulonglong2 w0 = s_ab[(4 * t + 0) * 32 + lane];   // lane-dist LDS.128
                ulonglong2 w1 = s_ab[(4 * t + 1) * 32 + lane];
                ulonglong2 w2 = s_ab[(4 * t + 2) * 32 + lane];
                ulonglong2 w3 = s_ab[(4 * t + 3) * 32 + lane];
                #pragma unroll
                for (int k = 0; k < 6; k++) {
                    float4 q = xl4[k * 16 + t];                  // broadcast LDS.128
                    ull x0 = pk(q.x, q.x), x1 = pk(q.y, q.y);
                    ull x2 = pk(q.z, q.z), x3 = pk(q.w, q.w);
                    accA[k] = fma2(x0, w0.x, accA[k]);  accB[k] = fma2(x0, w0.y, accB[k]);
                    accA[k] = fma2(x1, w1.x, accA[k]);  accB[k] = fma2(x1, w1.y, accB[k]);
                    accA[k] = fma2(x2, w2.x, accA[k]);  accB[k] = fma2(x2, w2.y, accB[k]);
                    accA[k] = fma2(x3, w3.x, accA[k]);  accB[k] = fma2(x3, w3.y, accB[k]);
                }
            }
        }
        ull CA[6], BB[6];
        #pragma unroll
        for (int k = 0; k < 6; k++) { CA[k] = add2(cp, accA[k]); BB[k] = accB[k]; }

        // ---- pair loop: h1 via SMEM broadcast, W2 in registers ----
        float accRow = 0.0f;
        int hpar = 0;
        #pragma unroll
        for (int i = 0; i < 6; i++) {
            #pragma unroll
            for (int j = i + 1; j < 6; j++) {
                float* hb = hw + hpar * 128; hpar ^= 1;
                {
                    float sa0, sa1, sb0, sb1;
                    upk(add2(CA[i], BB[j]), sa0, sa1);
                    upk(add2(CA[j], BB[i]), sb0, sb1);
                    hb[lane]      = softplus_f(sa0);
                    hb[lane + 32] = softplus_f(sa1);
                    hb[lane + 64] = softplus_f(sb0);
                    hb[lane + 96] = softplus_f(sb1);
                }
                __syncwarp();
                const float4* h4 = reinterpret_cast<const float4*>(hb);

                ull tA = pk(0.f, 0.f), tB = pk(0.f, 0.f);
                #pragma unroll
                for (int t = 0; t < 16; t++) {
                    float4 q = h4[t];                      // broadcast LDS.128
                    tA = fma2(pk(q.x, q.y), w2q[2 * t],     tA);
                    tB = fma2(pk(q.z, q.w), w2q[2 * t + 1], tB);
                }
                ull uA = pk(0.f, 0.f), uB = pk(0.f, 0.f);
                #pragma unroll
                for (int t = 0; t < 16; t++) {
                    float4 q = h4[16 + t];
                    uA = fma2(pk(q.x, q.y), w2q[2 * t],     uA);
                    uB = fma2(pk(q.z, q.w), w2q[2 * t + 1], uB);
                }
                float p0, p1, q0, q1;
                upk(add2(tA, tB), p0, p1);
                upk(add2(uA, uB), q0, q1);
                accRow += (softplus_f(p0 + p1 + b2l) + softplus_f(q0 + q1 + b2l)) * w3l;
            }
        }

        // ---- reduce over the 32 output-neuron lanes and write ----
        #pragma unroll
        for (int off = 16; off; off >>= 1)
            accRow += __shfl_xor_sync(FULLMASK, accRow, off);
        if (lane == 0)
            out[r] = 0.5f * accRow + 15.0f * b3v;
    }
}

extern "C" void kernel_launch(void* const* d_in, const int* in_sizes, int n_in,
                              void* d_out, int out_size) {
    const float* core = (const float*)d_in[0];
    const float* ligs = (const float*)d_in[1];
    const float* W1   = (const float*)d_in[2];
    const float* b1   = (const float*)d_in[3];
    const float* W2   = (const float*)d_in[4];
    const float* b2   = (const float*)d_in[5];
    const float* W3   = (const float*)d_in[6];
    const float* b3   = (const float*)d_in[7];
    float* out = (float*)d_out;

    const int B = in_sizes[0] / 64;   // 32768

    cudaFuncSetAttribute(three_body_kernel,
                         cudaFuncAttributeMaxDynamicSharedMemorySize, SMEM_BYTES);

    three_body_kernel<<<1024, 256, SMEM_BYTES>>>(
        core, ligs, W1, b1, W2, b2, W3, b3, out, B);
}

// round 4
// speedup vs baseline: 1.0442x; 1.0442x over previous
#include <cuda_runtime.h>

// ThreeBodyLayer — round 4: latency-restructured pair loop (3 groups of 5),
// batched softplus/STS, one syncwarp per phase, W2 in registers, f32x2 math.
//
// Factorized layer 1: cp = core@W1c + b1, A_k = lig_k@W1a, B_k = lig_k@W1b,
// CA_k = cp + A_k.  Per ordered pair (i,j): h1 = sp(CA_i + B_j);
// t = h1@W2 + b2; y += sp(t)·W3[m].  out = 0.5·Σy + 15·b3.

typedef unsigned long long ull;

#define FULLMASK 0xFFFFFFFFu

__device__ __forceinline__ ull pk(float lo, float hi) {
    ull r; asm("mov.b64 %0, {%1, %2};" : "=l"(r) : "f"(lo), "f"(hi)); return r;
}
__device__ __forceinline__ void upk(ull v, float& lo, float& hi) {
    asm("mov.b64 {%0, %1}, %2;" : "=f"(lo), "=f"(hi) : "l"(v));
}
__device__ __forceinline__ ull fma2(ull a, ull b, ull c) {
    ull d; asm("fma.rn.f32x2 %0, %1, %2, %3;" : "=l"(d) : "l"(a), "l"(b), "l"(c)); return d;
}
__device__ __forceinline__ ull add2(ull a, ull b) {
    ull d; asm("add.rn.f32x2 %0, %1, %2;" : "=l"(d) : "l"(a), "l"(b)); return d;
}
__device__ __forceinline__ float softplus_f(float x) {
    return fmaxf(x, 0.0f) + __logf(1.0f + __expf(-fabsf(x)));
}

// ---- dynamic SMEM layout ----
// [0,     16384)  ulonglong2 s_wc[32*32]    core-proj weights (2 packed pairs)
// [16384, 49152)  ulonglong2 s_ab[64*32]    {wa_pack, wb_pack} per (d,lane)
// [49152, 64000)  float      s_x [8][464]   staged x row per warp (448 used)
// [64000, 84480)  float      s_h [8][640]   5 h1 buffers (128 floats each) per warp
static constexpr int SMEM_BYTES = 84480;

__global__ void __launch_bounds__(256, 2) three_body_kernel(
    const float* __restrict__ core,   // [B, 64]
    const float* __restrict__ ligs,   // [B, 6, 64]
    const float* __restrict__ W1,     // [192, 64]
    const float* __restrict__ b1,     // [64]
    const float* __restrict__ W2,     // [64, 32]
    const float* __restrict__ b2,     // [32]
    const float* __restrict__ W3,     // [32]
    const float* __restrict__ b3,     // [1]
    float* __restrict__ out,          // [B]
    int B)
{
    extern __shared__ unsigned char sm[];
    ulonglong2* s_wc = reinterpret_cast<ulonglong2*>(sm);
    ulonglong2* s_ab = reinterpret_cast<ulonglong2*>(sm + 16384);
    float*      s_x  = reinterpret_cast<float*>(sm + 49152);
    float*      s_h  = reinterpret_cast<float*>(sm + 64000);

    // ---- stage weights (block-wide, once) ----
    for (int idx = threadIdx.x; idx < 1024; idx += 256) {
        int tp = idx >> 5, l = idx & 31;
        ulonglong2 v;
        v.x = pk(W1[(2 * tp)     * 64 + l], W1[(2 * tp)     * 64 + l + 32]);
        v.y = pk(W1[(2 * tp + 1) * 64 + l], W1[(2 * tp + 1) * 64 + l + 32]);
        s_wc[idx] = v;
    }
    for (int idx = threadIdx.x; idx < 2048; idx += 256) {
        int d = idx >> 5, l = idx & 31;
        ulonglong2 v;
        v.x = pk(W1[(64  + d) * 64 + l], W1[(64  + d) * 64 + l + 32]);
        v.y = pk(W1[(128 + d) * 64 + l], W1[(128 + d) * 64 + l + 32]);
        s_ab[idx] = v;
    }
    __syncthreads();

    const int lane = threadIdx.x & 31;
    const int warp = threadIdx.x >> 5;
    const int gw   = (blockIdx.x * 256 + threadIdx.x) >> 5;
    const int nw   = (gridDim.x * 256) >> 5;

    // ---- W2 column for lane m, packed over d-pairs (persistent registers) ----
    ull w2q[32];
    #pragma unroll
    for (int dp = 0; dp < 32; dp++)
        w2q[dp] = pk(W2[(2 * dp) * 32 + lane], W2[(2 * dp + 1) * 32 + lane]);

    const float b1a = b1[lane];
    const float b1b = b1[lane + 32];
    const float b2l = b2[lane];
    const float w3l = W3[lane];
    const float b3v = b3[0];

    float* xw = s_x + warp * 464;
    float* hw = s_h + warp * 640;   // 5 buffers x 128 floats

    // unordered pair tables (compile-time folded under full unroll)
    const int PI[15] = {0,0,0,0,0,1,1,1,1,2,2,2,3,3,4};
    const int PJ[15] = {1,2,3,4,5,2,3,4,5,3,4,5,4,5,5};

    for (int r = gw; r < B; r += nw) {
        // ---- stage x row: core(64) + ligs(384) as 112 float4 ----
        __syncwarp();
        {
            const float4* c4 = reinterpret_cast<const float4*>(core + (size_t)r * 64);
            const float4* l4 = reinterpret_cast<const float4*>(ligs + (size_t)r * 384);
            float4* x4 = reinterpret_cast<float4*>(xw);
            if (lane < 16) x4[lane] = c4[lane];
            #pragma unroll
            for (int t = 0; t < 3; t++) x4[16 + t * 32 + lane] = l4[t * 32 + lane];
        }
        __syncwarp();

        // ---- core projection: cp = core@W1c + b1 (packed halves) ----
        ull cpA = pk(b1a, b1b), cpB = pk(0.0f, 0.0f);
        {
            const float4* x4 = reinterpret_cast<const float4*>(xw);
            #pragma unroll
            for (int t = 0; t < 16; t++) {
                float4 q = x4[t];                          // broadcast LDS.128
                ulonglong2 w0 = s_wc[(2 * t)     * 32 + lane];
                ulonglong2 w1 = s_wc[(2 * t + 1) * 32 + lane];
                cpA = fma2(pk(q.x, q.x), w0.x, cpA);
                cpB = fma2(pk(q.y, q.y), w0.y, cpB);
                cpA = fma2(pk(q.z, q.z), w1.x, cpA);
                cpB = fma2(pk(q.w, q.w), w1.y, cpB);
            }
        }
        const ull cp = add2(cpA, cpB);

        // ---- lig projections: one d-quad of weights feeds all 6 ligands ----
        ull accA[6], accB[6];
        #pragma unroll
        for (int k = 0; k < 6; k++) { accA[k] = pk(0.f, 0.f); accB[k] = pk(0.f, 0.f); }
        {
            const float4* xl4 = reinterpret_cast<const float4*>(xw + 64);
            #pragma unroll 4
            for (int t = 0; t < 16; t++) {
                ulonglong2 w0 = s_ab[(4 * t + 0) * 32 + lane];   // lane-dist LDS.128
                ulonglong2 w1 = s_ab[(4 * t + 1) * 32 + lane];
                ulonglong2 w2 = s_ab[(4 * t + 2) * 32 + lane];
                ulonglong2 w3 = s_ab[(4 * t + 3) * 32 + lane];
                #pragma unroll
                for (int k = 0; k < 6; k++) {
                    float4 q = xl4[k * 16 + t];                  // broadcast LDS.128
                    ull x0 = pk(q.x, q.x), x1 = pk(q.y, q.y);
                    ull x2 = pk(q.z, q.z), x3 = pk(q.w, q.w);
                    accA[k] = fma2(x0, w0.x, accA[k]);  accB[k] = fma2(x0, w0.y, accB[k]);
                    accA[k] = fma2(x1, w1.x, accA[k]);  accB[k] = fma2(x1, w1.y, accB[k]);
                    accA[k] = fma2(x2, w2.x, accA[k]);  accB[k] = fma2(x2, w2.y, accB[k]);
                    accA[k] = fma2(x3, w3.x, accA[k]);  accB[k] = fma2(x3, w3.y, accB[k]);
                }
            }
        }
        ull CA[6], BB[6];
        #pragma unroll
        for (int k = 0; k < 6; k++) { CA[k] = add2(cp, accA[k]); BB[k] = accB[k]; }

        // ---- pair loop: 3 groups of 5 pairs; batch softplus+STS, 1 sync, 5 GEMVs ----
        float accRow = 0.0f;
        #pragma unroll
        for (int g = 0; g < 3; g++) {
            __syncwarp();   // previous group's LDS reads done before overwriting buffers
            #pragma unroll
            for (int p = 0; p < 5; p++) {
                const int i = PI[g * 5 + p], j = PJ[g * 5 + p];
                float* hb = hw + p * 128;
                float sa0, sa1, sb0, sb1;
                upk(add2(CA[i], BB[j]), sa0, sa1);
                upk(add2(CA[j], BB[i]), sb0, sb1);
                hb[lane]      = softplus_f(sa0);
                hb[lane + 32] = softplus_f(sa1);
                hb[lane + 64] = softplus_f(sb0);
                hb[lane + 96] = softplus_f(sb1);
            }
            __syncwarp();
            #pragma unroll
            for (int p = 0; p < 5; p++) {
                const float4* h4 = reinterpret_cast<const float4*>(hw + p * 128);
                ull tA = pk(0.f, 0.f), tB = pk(0.f, 0.f);
                ull uA = pk(0.f, 0.f), uB = pk(0.f, 0.f);
                #pragma unroll
                for (int t = 0; t < 16; t++) {
                    float4 q0 = h4[t];                     // h[0:64]   (order i,j)
                    float4 q1 = h4[16 + t];                // h[64:128] (order j,i)
                    tA = fma2(pk(q0.x, q0.y), w2q[2 * t],     tA);
                    tB = fma2(pk(q0.z, q0.w), w2q[2 * t + 1], tB);
                    uA = fma2(pk(q1.x, q1.y), w2q[2 * t],     uA);
                    uB = fma2(pk(q1.z, q1.w), w2q[2 * t + 1], uB);
                }
                float p0, p1, q0, q1;
                upk(add2(tA, tB), p0, p1);
                upk(add2(uA, uB), q0, q1);
                accRow += (softplus_f(p0 + p1 + b2l) + softplus_f(q0 + q1 + b2l)) * w3l;
            }
        }

        // ---- reduce over the 32 output-neuron lanes and write ----
        #pragma unroll
        for (int off = 16; off; off >>= 1)
            accRow += __shfl_xor_sync(FULLMASK, accRow, off);
        if (lane == 0)
            out[r] = 0.5f * accRow + 15.0f * b3v;
    }
}

extern "C" void kernel_launch(void* const* d_in, const int* in_sizes, int n_in,
                              void* d_out, int out_size) {
    const float* core = (const float*)d_in[0];
    const float* ligs = (const float*)d_in[1];
    const float* W1   = (const float*)d_in[2];
    const float* b1   = (const float*)d_in[3];
    const float* W2   = (const float*)d_in[4];
    const float* b2   = (const float*)d_in[5];
    const float* W3   = (const float*)d_in[6];
    const float* b3   = (const float*)d_in[7];
    float* out = (float*)d_out;

    const int B = in_sizes[0] / 64;   // 32768

    cudaFuncSetAttribute(three_body_kernel,
                         cudaFuncAttributeMaxDynamicSharedMemorySize, SMEM_BYTES);

    // 592 CTAs = 2 full waves at 2 CTAs/SM on 148 SMs; grid-stride over rows.
    three_body_kernel<<<592, 256, SMEM_BYTES>>>(
        core, ligs, W1, b1, W2, b2, W3, b3, out, B);
}

// round 6
// speedup vs baseline: 1.4638x; 1.4019x over previous
#include <cuda_runtime.h>
#include <cuda_bf16.h>
#include <cstdint>

// ThreeBodyLayer — round 6: layer 2 on tensor cores via mma.sync (sm_80+
// baseline PTX -> HMMA; tcgen05 is unavailable: harness targets sm_103,
// not sm_103a).
//
// Layer 1 (CUDA cores, warp-per-row, f32x2): cp = core@W1c + b1,
// A_k = lig_k@W1a, B_k = lig_k@W1b -> CA_k = cp+A_k, BB_k stored to SMEM.
// Layer 2 (HMMA): lane p = ordered pair p (30 real + 2 dummy). Lane builds
// h[p][0:64] = softplus(CA_i(p) + BB_j(p)) in fp32, splits to bf16 hi/lo,
// stores rows (144B stride, ldmatrix-conflict-free). Warp GEMM
// A[32x64] @ W2[64x32] as m16n8k16 tiles, 3-product bf16 split
// (hi*B1 + hi*B2 + lo*B1), W2 fragments resident in registers.
// Epilogue on C fragments: softplus(t+b2)@W3, dummy masking, shfl reduce.

typedef unsigned long long ull;
#define FULLMASK 0xFFFFFFFFu

__device__ __forceinline__ ull pk(float lo, float hi) {
    ull r; asm("mov.b64 %0, {%1, %2};" : "=l"(r) : "f"(lo), "f"(hi)); return r;
}
__device__ __forceinline__ void upk(ull v, float& lo, float& hi) {
    asm("mov.b64 {%0, %1}, %2;" : "=f"(lo), "=f"(hi) : "l"(v));
}
__device__ __forceinline__ ull fma2(ull a, ull b, ull c) {
    ull d; asm("fma.rn.f32x2 %0, %1, %2, %3;" : "=l"(d) : "l"(a), "l"(b), "l"(c)); return d;
}
__device__ __forceinline__ ull add2(ull a, ull b) {
    ull d; asm("add.rn.f32x2 %0, %1, %2;" : "=l"(d) : "l"(a), "l"(b)); return d;
}
__device__ __forceinline__ float softplus_f(float x) {
    return fmaxf(x, 0.0f) + __logf(1.0f + __expf(-fabsf(x)));
}
__device__ __forceinline__ uint32_t smem_u32(const void* p) {
    uint32_t a;
    asm("{ .reg .u64 t; cvta.to.shared.u64 t, %1; cvt.u32.u64 %0, t; }"
        : "=r"(a) : "l"(p));
    return a;
}
// pack two f32 to bf16x2: hi half = a, lo half = b
__device__ __forceinline__ uint32_t pkbf(float a, float b) {
    uint32_t r; asm("cvt.rn.bf16x2.f32 %0, %1, %2;" : "=r"(r) : "f"(a), "f"(b));
    return r;
}
__device__ __forceinline__ void ldsm4(uint32_t* r, uint32_t addr) {
    asm volatile("ldmatrix.sync.aligned.m8n8.x4.shared.b16 {%0,%1,%2,%3}, [%4];"
                 : "=r"(r[0]), "=r"(r[1]), "=r"(r[2]), "=r"(r[3]) : "r"(addr));
}
__device__ __forceinline__ void mma_bf16(float* c, const uint32_t* a,
                                         uint32_t b0, uint32_t b1) {
    asm volatile(
        "mma.sync.aligned.m16n8k16.row.col.f32.bf16.bf16.f32 "
        "{%0,%1,%2,%3}, {%4,%5,%6,%7}, {%8,%9}, {%0,%1,%2,%3};"
        : "+f"(c[0]), "+f"(c[1]), "+f"(c[2]), "+f"(c[3])
        : "r"(a[0]), "r"(a[1]), "r"(a[2]), "r"(a[3]), "r"(b0), "r"(b1));
}

// ---- SMEM layout (bytes), 1 CTA of 256 threads (8 warps) ----
static constexpr int S_WC  = 0;        // ulonglong2[32*32] core-proj W  (16384)
static constexpr int S_AB  = 16384;    // ulonglong2[64*32] lig-proj W   (32768)
static constexpr int S_CAB = 49152;    // float [8][12*68]  CA/BB        (26112)
static constexpr int S_X   = 75264;    // float [8][464]    x staging    (14848)
static constexpr int S_HI  = 90112;    // bf16  [8][32 rows x 72]        (36864)
static constexpr int S_LO  = 126976;   // bf16  [8][32 rows x 72]        (36864)
static constexpr int SMEM_BYTES = 163840;

__global__ void __launch_bounds__(256) three_body_kernel(
    const float* __restrict__ core,   // [B, 64]
    const float* __restrict__ ligs,   // [B, 6, 64]
    const float* __restrict__ W1,     // [192, 64]
    const float* __restrict__ b1,     // [64]
    const float* __restrict__ W2,     // [64, 32]
    const float* __restrict__ b2,     // [32]
    const float* __restrict__ W3,     // [32]
    const float* __restrict__ b3,     // [1]
    float* __restrict__ out,          // [B]
    int B)
{
    extern __shared__ unsigned char sm[];
    ulonglong2* s_wc = reinterpret_cast<ulonglong2*>(sm + S_WC);
    ulonglong2* s_ab = reinterpret_cast<ulonglong2*>(sm + S_AB);
    float*      s_cb = reinterpret_cast<float*>(sm + S_CAB);
    float*      s_x  = reinterpret_cast<float*>(sm + S_X);

    const uint32_t smem_base = smem_u32(sm);
    const int tid  = threadIdx.x;
    const int lane = tid & 31;
    const int wid  = tid >> 5;

    // ---- stage layer-1 weights (block-wide, once) ----
    for (int idx = tid; idx < 1024; idx += 256) {
        int tp = idx >> 5, l = idx & 31;
        ulonglong2 v;
        v.x = pk(W1[(2 * tp)     * 64 + l], W1[(2 * tp)     * 64 + l + 32]);
        v.y = pk(W1[(2 * tp + 1) * 64 + l], W1[(2 * tp + 1) * 64 + l + 32]);
        s_wc[idx] = v;
    }
    for (int idx = tid; idx < 2048; idx += 256) {
        int d = idx >> 5, l = idx & 31;
        ulonglong2 v;
        v.x = pk(W1[(64  + d) * 64 + l], W1[(64  + d) * 64 + l + 32]);
        v.y = pk(W1[(128 + d) * 64 + l], W1[(128 + d) * 64 + l + 32]);
        s_ab[idx] = v;
    }
    __syncthreads();

    // ---- W2 fragments in registers: B1 = bf16(W2), B2 = residual ----
    // m16n8k16 .col B frag: b0 = {W2[k0][n], W2[k0+1][n]}, b1 = {k0+8, k0+9}
    uint32_t B1f[4][4][2], B2f[4][4][2];
    {
        const int krow = (lane & 3) * 2;
        const int ncol = lane >> 2;
        #pragma unroll
        for (int kt = 0; kt < 4; kt++) {
            #pragma unroll
            for (int nt = 0; nt < 4; nt++) {
                int k0 = kt * 16 + krow, n = nt * 8 + ncol;
                float w00 = W2[(k0 + 0) * 32 + n], w01 = W2[(k0 + 1) * 32 + n];
                float w08 = W2[(k0 + 8) * 32 + n], w09 = W2[(k0 + 9) * 32 + n];
                uint32_t h0 = pkbf(w01, w00);
                uint32_t h1 = pkbf(w09, w08);
                float r00 = w00 - __uint_as_float(h0 << 16);
                float r01 = w01 - __uint_as_float(h0 & 0xFFFF0000u);
                float r08 = w08 - __uint_as_float(h1 << 16);
                float r09 = w09 - __uint_as_float(h1 & 0xFFFF0000u);
                B1f[kt][nt][0] = h0;  B1f[kt][nt][1] = h1;
                B2f[kt][nt][0] = pkbf(r01, r00);
                B2f[kt][nt][1] = pkbf(r09, r08);
            }
        }
    }
    // per-lane epilogue constants: n = nt*8 + (lane&3)*2 + e
    float b2v[8], w3v[8];
    #pragma unroll
    for (int nt = 0; nt < 4; nt++) {
        #pragma unroll
        for (int e = 0; e < 2; e++) {
            int n = nt * 8 + (lane & 3) * 2 + e;
            b2v[nt * 2 + e] = b2[n];
            w3v[nt * 2 + e] = W3[n];
        }
    }
    // pair table: lane = ordered pair p
    int pi, pj;
    if (lane < 30) { pi = lane / 5; int jj = lane % 5; pj = jj + (jj >= pi ? 1 : 0); }
    else           { pi = 0; pj = 1; }

    const float b1a = b1[lane];
    const float b1b = b1[lane + 32];
    const float b3v = b3[0];

    float* xw  = s_x  + wid * 464;
    float* cab = s_cb + wid * 816;                      // 12 vecs x 68 floats
    char*  hrow = (char*)sm + S_HI + wid * 4608 + lane * 144;
    char*  lrow = (char*)sm + S_LO + wid * 4608 + lane * 144;
    const uint32_t hibase = smem_base + S_HI + wid * 4608;
    const uint32_t lobase = smem_base + S_LO + wid * 4608;
    const uint32_t roff   = (uint32_t)(lane & 15) * 144 + (uint32_t)(lane >> 4) * 16;

    const int gw = blockIdx.x * 8 + wid;
    const int nw = gridDim.x * 8;

    for (int r = gw; r < B; r += nw) {
        // ---- stage x row ----
        __syncwarp();
        {
            const float4* c4 = reinterpret_cast<const float4*>(core + (size_t)r * 64);
            const float4* l4 = reinterpret_cast<const float4*>(ligs + (size_t)r * 384);
            float4* x4 = reinterpret_cast<float4*>(xw);
            if (lane < 16) x4[lane] = c4[lane];
            #pragma unroll
            for (int t = 0; t < 3; t++) x4[16 + t * 32 + lane] = l4[t * 32 + lane];
        }
        __syncwarp();

        // ---- layer 1: core projection ----
        ull cpA = pk(b1a, b1b), cpB = pk(0.0f, 0.0f);
        {
            const float4* x4 = reinterpret_cast<const float4*>(xw);
            #pragma unroll
            for (int t = 0; t < 16; t++) {
                float4 q = x4[t];
                ulonglong2 w0 = s_wc[(2 * t)     * 32 + lane];
                ulonglong2 w1 = s_wc[(2 * t + 1) * 32 + lane];
                cpA = fma2(pk(q.x, q.x), w0.x, cpA);
                cpB = fma2(pk(q.y, q.y), w0.y, cpB);
                cpA = fma2(pk(q.z, q.z), w1.x, cpA);
                cpB = fma2(pk(q.w, q.w), w1.y, cpB);
            }
        }
        const ull cp = add2(cpA, cpB);

        // ---- layer 1: lig projections ----
        ull accA[6], accB[6];
        #pragma unroll
        for (int k = 0; k < 6; k++) { accA[k] = pk(0.f, 0.f); accB[k] = pk(0.f, 0.f); }
        {
            const float4* xl4 = reinterpret_cast<const float4*>(xw + 64);
            #pragma unroll 4
            for (int t = 0; t < 16; t++) {
                ulonglong2 w0 = s_ab[(4 * t + 0) * 32 + lane];
                ulonglong2 w1 = s_ab[(4 * t + 1) * 32 + lane];
                ulonglong2 w2 = s_ab[(4 * t + 2) * 32 + lane];
                ulonglong2 w3 = s_ab[(4 * t + 3) * 32 + lane];
                #pragma unroll
                for (int k = 0; k < 6; k++) {
                    float4 q = xl4[k * 16 + t];
                    ull x0 = pk(q.x, q.x), x1 = pk(q.y, q.y);
                    ull x2 = pk(q.z, q.z), x3 = pk(q.w, q.w);
                    accA[k] = fma2(x0, w0.x, accA[k]);  accB[k] = fma2(x0, w0.y, accB[k]);
                    accA[k] = fma2(x1, w1.x, accA[k]);  accB[k] = fma2(x1, w1.y, accB[k]);
                    accA[k] = fma2(x2, w2.x, accA[k]);  accB[k] = fma2(x2, w2.y, accB[k]);
                    accA[k] = fma2(x3, w3.x, accA[k]);  accB[k] = fma2(x3, w3.y, accB[k]);
                }
            }
        }
        // ---- write CA/BB to SMEM (lane owns d=lane and d=lane+32) ----
        __syncwarp();   // prior row's h-build reads of cab are done
        #pragma unroll
        for (int k = 0; k < 6; k++) {
            float lo, hi;
            upk(add2(cp, accA[k]), lo, hi);
            cab[k * 68 + lane] = lo;  cab[k * 68 + 32 + lane] = hi;
            upk(accB[k], lo, hi);
            cab[(6 + k) * 68 + lane] = lo;  cab[(6 + k) * 68 + 32 + lane] = hi;
        }
        __syncwarp();

        // ---- h build: lane p computes h[p][0:64], split bf16 hi/lo ----
        {
            const float* vA = cab + pi * 68;
            const float* vB = cab + (6 + pj) * 68;
            #pragma unroll
            for (int q2 = 0; q2 < 8; q2++) {          // 8 d per iteration
                uint32_t hb[4], lb[4];
                #pragma unroll
                for (int h = 0; h < 2; h++) {
                    int q = q2 * 2 + h;
                    float4 a = *reinterpret_cast<const float4*>(vA + q * 4);
                    float4 b = *reinterpret_cast<const float4*>(vB + q * 4);
                    float h0 = softplus_f(a.x + b.x), h1 = softplus_f(a.y + b.y);
                    float h2 = softplus_f(a.z + b.z), h3 = softplus_f(a.w + b.w);
                    uint32_t p0 = pkbf(h1, h0);
                    uint32_t p1 = pkbf(h3, h2);
                    float l0 = h0 - __uint_as_float(p0 << 16);
                    float l1 = h1 - __uint_as_float(p0 & 0xFFFF0000u);
                    float l2 = h2 - __uint_as_float(p1 << 16);
                    float l3 = h3 - __uint_as_float(p1 & 0xFFFF0000u);
                    hb[h * 2] = p0;  hb[h * 2 + 1] = p1;
                    lb[h * 2] = pkbf(l1, l0);  lb[h * 2 + 1] = pkbf(l3, l2);
                }
                *reinterpret_cast<uint4*>(hrow + q2 * 16) =
                    make_uint4(hb[0], hb[1], hb[2], hb[3]);
                *reinterpret_cast<uint4*>(lrow + q2 * 16) =
                    make_uint4(lb[0], lb[1], lb[2], lb[3]);
            }
        }
        __syncwarp();

        // ---- layer 2 GEMM: A[32x64] @ W2[64x32], 3-product bf16 split ----
        float acc[2][4][4];
        #pragma unroll
        for (int mt = 0; mt < 2; mt++)
            #pragma unroll
            for (int nt = 0; nt < 4; nt++)
                #pragma unroll
                for (int e = 0; e < 4; e++) acc[mt][nt][e] = 0.0f;

        #pragma unroll
        for (int mt = 0; mt < 2; mt++) {
            #pragma unroll
            for (int kt = 0; kt < 4; kt++) {
                uint32_t af[4];
                ldsm4(af, hibase + (uint32_t)mt * 2304 + roff + (uint32_t)kt * 32);
                #pragma unroll
                for (int nt = 0; nt < 4; nt++)
                    mma_bf16(acc[mt][nt], af, B1f[kt][nt][0], B1f[kt][nt][1]);
                #pragma unroll
                for (int nt = 0; nt < 4; nt++)
                    mma_bf16(acc[mt][nt], af, B2f[kt][nt][0], B2f[kt][nt][1]);
                ldsm4(af, lobase + (uint32_t)mt * 2304 + roff + (uint32_t)kt * 32);
                #pragma unroll
                for (int nt = 0; nt < 4; nt++)
                    mma_bf16(acc[mt][nt], af, B1f[kt][nt][0], B1f[kt][nt][1]);
            }
        }

        // ---- epilogue: y = softplus(t + b2) @ W3, mask dummies, reduce ----
        float total = 0.0f;
        #pragma unroll
        for (int mt = 0; mt < 2; mt++) {
            #pragma unroll
            for (int hf = 0; hf < 2; hf++) {
                int prow = mt * 16 + (lane >> 2) + hf * 8;
                float part = 0.0f;
                #pragma unroll
                for (int nt = 0; nt < 4; nt++) {
                    #pragma unroll
                    for (int e = 0; e < 2; e++)
                        part += softplus_f(acc[mt][nt][hf * 2 + e] + b2v[nt * 2 + e])
                                * w3v[nt * 2 + e];
                }
                if (prow < 30) total += part;
            }
        }
        #pragma unroll
        for (int off = 16; off; off >>= 1)
            total += __shfl_xor_sync(FULLMASK, total, off);
        if (lane == 0)
            out[r] = 0.5f * total + 15.0f * b3v;
    }
}

extern "C" void kernel_launch(void* const* d_in, const int* in_sizes, int n_in,
                              void* d_out, int out_size) {
    const float* core = (const float*)d_in[0];
    const float* ligs = (const float*)d_in[1];
    const float* W1   = (const float*)d_in[2];
    const float* b1   = (const float*)d_in[3];
    const float* W2   = (const float*)d_in[4];
    const float* b2   = (const float*)d_in[5];
    const float* W3   = (const float*)d_in[6];
    const float* b3   = (const float*)d_in[7];
    float* out = (float*)d_out;

    const int B = in_sizes[0] / 64;   // 32768

    cudaFuncSetAttribute(three_body_kernel,
                         cudaFuncAttributeMaxDynamicSharedMemorySize, SMEM_BYTES);

    three_body_kernel<<<148, 256, SMEM_BYTES>>>(
        core, ligs, W1, b1, W2, b2, W3, b3, out, B);
}

// round 7
// speedup vs baseline: 1.8324x; 1.2518x over previous
#include <cuda_runtime.h>
#include <cuda_bf16.h>
#include <cstdint>

// ThreeBodyLayer — round 7: BOTH layers on tensor cores (mma.sync bf16).
//
// CTA-cooperative, group of 16 batch rows per iteration, 8 warps.
// Phase 1 (layer 1 GEMM): warps 0-5: ligand k projections
//   [16 rows,64] @ W1ab^T -> A_k, B_k (n=128); warps 6-7: core proj (+b1).
//   A = x in bf16 (hi only; quant err ~1e-4 final), B = W1 in bf16 hi+lo
//   (2-product exact weights). C scattered to shared cab[16][13][68] f32.
// Phase 2 (h + layer 2): warp w owns rows 2w,2w+1. Lane p = ordered pair p:
//   h = softplus(cp + A_i + B_j) built from cab, split bf16 hi/lo, stored
//   at 144B stride; warp GEMM A[32x64]@W2[64x32] with 3-product split,
//   W2 fragments register-resident; epilogue softplus(t+b2)@W3, masked,
//   shfl-reduced (identical to validated round 6).

#define FULLMASK 0xFFFFFFFFu

__device__ __forceinline__ float softplus_f(float x) {
    return fmaxf(x, 0.0f) + __logf(1.0f + __expf(-fabsf(x)));
}
__device__ __forceinline__ uint32_t smem_u32(const void* p) {
    uint32_t a;
    asm("{ .reg .u64 t; cvta.to.shared.u64 t, %1; cvt.u32.u64 %0, t; }"
        : "=r"(a) : "l"(p));
    return a;
}
// pack two f32 to bf16x2: hi half = a, lo half = b
__device__ __forceinline__ uint32_t pkbf(float a, float b) {
    uint32_t r; asm("cvt.rn.bf16x2.f32 %0, %1, %2;" : "=r"(r) : "f"(a), "f"(b));
    return r;
}
__device__ __forceinline__ void ldsm4(uint32_t* r, uint32_t addr) {
    asm volatile("ldmatrix.sync.aligned.m8n8.x4.shared.b16 {%0,%1,%2,%3}, [%4];"
                 : "=r"(r[0]), "=r"(r[1]), "=r"(r[2]), "=r"(r[3]) : "r"(addr));
}
__device__ __forceinline__ void mma_bf16(float* c, const uint32_t* a,
                                         uint32_t b0, uint32_t b1) {
    asm volatile(
        "mma.sync.aligned.m16n8k16.row.col.f32.bf16.bf16.f32 "
        "{%0,%1,%2,%3}, {%4,%5,%6,%7}, {%8,%9}, {%0,%1,%2,%3};"
        : "+f"(c[0]), "+f"(c[1]), "+f"(c[2]), "+f"(c[3])
        : "r"(a[0]), "r"(a[1]), "r"(a[2]), "r"(a[3]), "r"(b0), "r"(b1));
}

// ---- SMEM layout (bytes) ----
// W1T: [192 n'][64 k] bf16, row stride 144B. n' 0..63: A-proj (W1 rows 64+k),
// 64..127: B-proj (W1 rows 128+k), 128..191: core (W1 rows k).
static constexpr int S_W1H = 0;        // 27648
static constexpr int S_W1L = 27648;    // 27648
static constexpr int S_CAB = 55296;    // float[16 rows][13 vecs][68] = 56576
static constexpr int S_B1  = 111872;   // float[64] = 256
static constexpr int S_HI  = 112128;   // bf16 h-hi: 8 warps x 32x144B = 36864
static constexpr int S_LO  = 148992;   // bf16 h-lo: 36864
static constexpr int SMEM_BYTES = 185856;

__global__ void __launch_bounds__(256) three_body_kernel(
    const float* __restrict__ core,   // [B, 64]
    const float* __restrict__ ligs,   // [B, 6, 64]
    const float* __restrict__ W1,     // [192, 64]
    const float* __restrict__ b1,     // [64]
    const float* __restrict__ W2,     // [64, 32]
    const float* __restrict__ b2,     // [32]
    const float* __restrict__ W3,     // [32]
    const float* __restrict__ b3,     // [1]
    float* __restrict__ out,          // [B]
    int B)
{
    extern __shared__ unsigned char sm[];
    float* s_cab = reinterpret_cast<float*>(sm + S_CAB);
    float* s_b1  = reinterpret_cast<float*>(sm + S_B1);

    const uint32_t smem_base = smem_u32(sm);
    const int tid  = threadIdx.x;
    const int lane = tid & 31;
    const int wid  = tid >> 5;

    // ---- stage W1^T hi/lo (bf16) ----
    for (int idx = tid; idx < 12288; idx += 256) {
        int n = idx >> 6, k = idx & 63;
        float w;
        if      (n < 64)  w = W1[(64  + k) * 64 + n];
        else if (n < 128) w = W1[(128 + k) * 64 + (n - 64)];
        else              w = W1[k * 64 + (n - 128)];
        __nv_bfloat16 h = __float2bfloat16(w);
        float res = w - __bfloat162float(h);
        *reinterpret_cast<__nv_bfloat16*>(sm + S_W1H + n * 144 + k * 2) = h;
        *reinterpret_cast<__nv_bfloat16*>(sm + S_W1L + n * 144 + k * 2) =
            __float2bfloat16(res);
    }
    if (tid < 64) s_b1[tid] = b1[tid];

    // ---- W2 fragments in registers: B1 = bf16(W2), B2 = residual ----
    uint32_t B1f[4][4][2], B2f[4][4][2];
    {
        const int krow = (lane & 3) * 2;
        const int ncol = lane >> 2;
        #pragma unroll
        for (int kt = 0; kt < 4; kt++) {
            #pragma unroll
            for (int nt = 0; nt < 4; nt++) {
                int k0 = kt * 16 + krow, n = nt * 8 + ncol;
                float w00 = W2[(k0 + 0) * 32 + n], w01 = W2[(k0 + 1) * 32 + n];
                float w08 = W2[(k0 + 8) * 32 + n], w09 = W2[(k0 + 9) * 32 + n];
                uint32_t h0 = pkbf(w01, w00);
                uint32_t h1 = pkbf(w09, w08);
                float r00 = w00 - __uint_as_float(h0 << 16);
                float r01 = w01 - __uint_as_float(h0 & 0xFFFF0000u);
                float r08 = w08 - __uint_as_float(h1 << 16);
                float r09 = w09 - __uint_as_float(h1 & 0xFFFF0000u);
                B1f[kt][nt][0] = h0;  B1f[kt][nt][1] = h1;
                B2f[kt][nt][0] = pkbf(r01, r00);
                B2f[kt][nt][1] = pkbf(r09, r08);
            }
        }
    }
    float b2v[8], w3v[8];
    #pragma unroll
    for (int nt = 0; nt < 4; nt++)
        #pragma unroll
        for (int e = 0; e < 2; e++) {
            int n = nt * 8 + (lane & 3) * 2 + e;
            b2v[nt * 2 + e] = b2[n];
            w3v[nt * 2 + e] = W3[n];
        }
    int pi, pj;
    if (lane < 30) { pi = lane / 5; int jj = lane % 5; pj = jj + (jj >= pi ? 1 : 0); }
    else           { pi = 0; pj = 1; }

    const float b3v = b3[0];
    const int   r0  = lane >> 2;          // fragment row within m16
    const int   c0  = (lane & 3) * 2;     // fragment col pair base

    const uint32_t hibase = smem_base + S_HI + wid * 4608;
    const uint32_t lobase = smem_base + S_LO + wid * 4608;
    char* hrow = (char*)sm + S_HI + wid * 4608 + lane * 144;
    char* lrow = (char*)sm + S_LO + wid * 4608 + lane * 144;
    const uint32_t roff = (uint32_t)(lane & 15) * 144 + (uint32_t)(lane >> 4) * 16;
    const uint32_t bmat = smem_base + S_W1H + roff;   // ldsm base for W1T hi

    const int n_groups = B >> 4;   // 2048

    __syncthreads();

    for (int g = blockIdx.x; g < n_groups; g += gridDim.x) {
        const int rbase = g << 4;
        __syncthreads();   // previous group's phase-2 cab reads complete

        // ================= phase 1: layer-1 GEMMs =================
        if (wid < 6) {
            const int k = wid;   // ligand index
            const float* xb = ligs + (size_t)rbase * 384 + k * 64;
            uint32_t af[4][4];
            #pragma unroll
            for (int kt = 0; kt < 4; kt++) {
                int c = kt * 16 + c0;
                float2 x00 = *reinterpret_cast<const float2*>(xb + (size_t)r0 * 384 + c);
                float2 x10 = *reinterpret_cast<const float2*>(xb + (size_t)(r0 + 8) * 384 + c);
                float2 x01 = *reinterpret_cast<const float2*>(xb + (size_t)r0 * 384 + c + 8);
                float2 x11 = *reinterpret_cast<const float2*>(xb + (size_t)(r0 + 8) * 384 + c + 8);
                af[kt][0] = pkbf(x00.y, x00.x);  af[kt][1] = pkbf(x10.y, x10.x);
                af[kt][2] = pkbf(x01.y, x01.x);  af[kt][3] = pkbf(x11.y, x11.x);
            }
            #pragma unroll
            for (int np = 0; np < 8; np++) {
                float a0[4] = {0.f, 0.f, 0.f, 0.f}, a1[4] = {0.f, 0.f, 0.f, 0.f};
                #pragma unroll
                for (int kt = 0; kt < 4; kt++) {
                    uint32_t bh[4], bl[4];
                    uint32_t adr = bmat + (uint32_t)np * 2304 + (uint32_t)kt * 32;
                    ldsm4(bh, adr);
                    ldsm4(bl, adr + (S_W1L - S_W1H));
                    mma_bf16(a0, af[kt], bh[0], bh[2]);
                    mma_bf16(a0, af[kt], bl[0], bl[2]);
                    mma_bf16(a1, af[kt], bh[1], bh[3]);
                    mma_bf16(a1, af[kt], bl[1], bl[3]);
                }
                #pragma unroll
                for (int ntl = 0; ntl < 2; ntl++) {
                    const float* a = ntl ? a1 : a0;
                    int n = np * 16 + ntl * 8 + c0;
                    int vec = (n < 64) ? k : 6 + k;
                    int d = n & 63;
                    *reinterpret_cast<float2*>(s_cab + ((r0)     * 13 + vec) * 68 + d) =
                        make_float2(a[0], a[1]);
                    *reinterpret_cast<float2*>(s_cab + ((r0 + 8) * 13 + vec) * 68 + d) =
                        make_float2(a[2], a[3]);
                }
            }
        } else {
            // core projection: warps 6,7 split n-range; W1T rows 128+
            const float* xb = core + (size_t)rbase * 64;
            uint32_t af[4][4];
            #pragma unroll
            for (int kt = 0; kt < 4; kt++) {
                int c = kt * 16 + c0;
                float2 x00 = *reinterpret_cast<const float2*>(xb + (size_t)r0 * 64 + c);
                float2 x10 = *reinterpret_cast<const float2*>(xb + (size_t)(r0 + 8) * 64 + c);
                float2 x01 = *reinterpret_cast<const float2*>(xb + (size_t)r0 * 64 + c + 8);
                float2 x11 = *reinterpret_cast<const float2*>(xb + (size_t)(r0 + 8) * 64 + c + 8);
                af[kt][0] = pkbf(x00.y, x00.x);  af[kt][1] = pkbf(x10.y, x10.x);
                af[kt][2] = pkbf(x01.y, x01.x);  af[kt][3] = pkbf(x11.y, x11.x);
            }
            #pragma unroll
            for (int npl = 0; npl < 2; npl++) {
                int np = (wid - 6) * 2 + npl;
                float a0[4] = {0.f, 0.f, 0.f, 0.f}, a1[4] = {0.f, 0.f, 0.f, 0.f};
                #pragma unroll
                for (int kt = 0; kt < 4; kt++) {
                    uint32_t bh[4], bl[4];
                    uint32_t adr = bmat + (uint32_t)(128 + np * 16) * 144 + (uint32_t)kt * 32;
                    ldsm4(bh, adr);
                    ldsm4(bl, adr + (S_W1L - S_W1H));
                    mma_bf16(a0, af[kt], bh[0], bh[2]);
                    mma_bf16(a0, af[kt], bl[0], bl[2]);
                    mma_bf16(a1, af[kt], bh[1], bh[3]);
                    mma_bf16(a1, af[kt], bl[1], bl[3]);
                }
                #pragma unroll
                for (int ntl = 0; ntl < 2; ntl++) {
                    const float* a = ntl ? a1 : a0;
                    int d = np * 16 + ntl * 8 + c0;   // n == d for core
                    float bb0 = s_b1[d], bb1 = s_b1[d + 1];
                    *reinterpret_cast<float2*>(s_cab + ((r0)     * 13 + 12) * 68 + d) =
                        make_float2(a[0] + bb0, a[1] + bb1);
                    *reinterpret_cast<float2*>(s_cab + ((r0 + 8) * 13 + 12) * 68 + d) =
                        make_float2(a[2] + bb0, a[3] + bb1);
                }
            }
        }
        __syncthreads();   // cab complete

        // ================= phase 2: h-build + layer-2 GEMM, 2 rows =================
        #pragma unroll
        for (int rr = 0; rr < 2; rr++) {
            const int row = wid * 2 + rr;
            const float* vA = s_cab + (row * 13 + pi) * 68;
            const float* vB = s_cab + (row * 13 + 6 + pj) * 68;
            const float* vC = s_cab + (row * 13 + 12) * 68;

            #pragma unroll
            for (int q2 = 0; q2 < 8; q2++) {
                uint32_t hb[4], lb[4];
                #pragma unroll
                for (int h = 0; h < 2; h++) {
                    int q = q2 * 2 + h;
                    float4 a = *reinterpret_cast<const float4*>(vA + q * 4);
                    float4 b = *reinterpret_cast<const float4*>(vB + q * 4);
                    float4 c = *reinterpret_cast<const float4*>(vC + q * 4);
                    float h0 = softplus_f(a.x + b.x + c.x);
                    float h1 = softplus_f(a.y + b.y + c.y);
                    float h2 = softplus_f(a.z + b.z + c.z);
                    float h3 = softplus_f(a.w + b.w + c.w);
                    uint32_t p0 = pkbf(h1, h0);
                    uint32_t p1 = pkbf(h3, h2);
                    float l0 = h0 - __uint_as_float(p0 << 16);
                    float l1 = h1 - __uint_as_float(p0 & 0xFFFF0000u);
                    float l2 = h2 - __uint_as_float(p1 << 16);
                    float l3 = h3 - __uint_as_float(p1 & 0xFFFF0000u);
                    hb[h * 2] = p0;  hb[h * 2 + 1] = p1;
                    lb[h * 2] = pkbf(l1, l0);  lb[h * 2 + 1] = pkbf(l3, l2);
                }
                *reinterpret_cast<uint4*>(hrow + q2 * 16) =
                    make_uint4(hb[0], hb[1], hb[2], hb[3]);
                *reinterpret_cast<uint4*>(lrow + q2 * 16) =
                    make_uint4(lb[0], lb[1], lb[2], lb[3]);
            }
            __syncwarp();

            float acc[2][4][4];
            #pragma unroll
            for (int mt = 0; mt < 2; mt++)
                #pragma unroll
                for (int nt = 0; nt < 4; nt++)
                    #pragma unroll
                    for (int e = 0; e < 4; e++) acc[mt][nt][e] = 0.0f;

            #pragma unroll
            for (int mt = 0; mt < 2; mt++) {
                #pragma unroll
                for (int kt = 0; kt < 4; kt++) {
                    uint32_t afr[4];
                    ldsm4(afr, hibase + (uint32_t)mt * 2304 + roff + (uint32_t)kt * 32);
                    #pragma unroll
                    for (int nt = 0; nt < 4; nt++)
                        mma_bf16(acc[mt][nt], afr, B1f[kt][nt][0], B1f[kt][nt][1]);
                    #pragma unroll
                    for (int nt = 0; nt < 4; nt++)
                        mma_bf16(acc[mt][nt], afr, B2f[kt][nt][0], B2f[kt][nt][1]);
                    ldsm4(afr, lobase + (uint32_t)mt * 2304 + roff + (uint32_t)kt * 32);
                    #pragma unroll
                    for (int nt = 0; nt < 4; nt++)
                        mma_bf16(acc[mt][nt], afr, B1f[kt][nt][0], B1f[kt][nt][1]);
                }
            }

            float total = 0.0f;
            #pragma unroll
            for (int mt = 0; mt < 2; mt++) {
                #pragma unroll
                for (int hf = 0; hf < 2; hf++) {
                    int prow = mt * 16 + (lane >> 2) + hf * 8;
                    float part = 0.0f;
                    #pragma unroll
                    for (int nt = 0; nt < 4; nt++)
                        #pragma unroll
                        for (int e = 0; e < 2; e++)
                            part += softplus_f(acc[mt][nt][hf * 2 + e] + b2v[nt * 2 + e])
                                    * w3v[nt * 2 + e];
                    if (prow < 30) total += part;
                }
            }
            #pragma unroll
            for (int off = 16; off; off >>= 1)
                total += __shfl_xor_sync(FULLMASK, total, off);
            if (lane == 0)
                out[rbase + row] = 0.5f * total + 15.0f * b3v;
            __syncwarp();   // h buffers free for next row
        }
    }
}

extern "C" void kernel_launch(void* const* d_in, const int* in_sizes, int n_in,
                              void* d_out, int out_size) {
    const float* core = (const float*)d_in[0];
    const float* ligs = (const float*)d_in[1];
    const float* W1   = (const float*)d_in[2];
    const float* b1   = (const float*)d_in[3];
    const float* W2   = (const float*)d_in[4];
    const float* b2   = (const float*)d_in[5];
    const float* W3   = (const float*)d_in[6];
    const float* b3   = (const float*)d_in[7];
    float* out = (float*)d_out;

    const int B = in_sizes[0] / 64;   // 32768

    cudaFuncSetAttribute(three_body_kernel,
                         cudaFuncAttributeMaxDynamicSharedMemorySize, SMEM_BYTES);

    three_body_kernel<<<148, 256, SMEM_BYTES>>>(
        core, ligs, W1, b1, W2, b2, W3, b3, out, B);
}

// round 8
// speedup vs baseline: 1.9590x; 1.0691x over previous
#include <cuda_runtime.h>
#include <cuda_bf16.h>
#include <cstdint>

// ThreeBodyLayer — round 8: 2 CTAs/SM (128 thr, 8-row groups), both layers
// on mma.sync bf16. Single h buffer per warp (hi stored/GEMMed, then lo from
// registers), cutting SMEM to ~102KB so two CTAs co-reside and their barriers
// interleave.
//
// Phase 1: warps 0-2: ligand pair (2w, 2w+1) stacked as M=16 @ W1ab^T
//   (n=128, x bf16-hi, W1 bf16 hi+lo 2-product). Warp 3: core proj + b1.
//   C scattered to cab[8 rows][13 vecs][68] f32.
// Phase 2: warp w owns rows 2w, 2w+1. Lane p = ordered pair p: h =
//   softplus(cp + A_i + B_j), split bf16 hi/lo; GEMM A[32x64]@W2[64x32]
//   3-product split, W2 fragments in registers; epilogue softplus(t+b2)@W3.

#define FULLMASK 0xFFFFFFFFu

__device__ __forceinline__ float softplus_f(float x) {
    return fmaxf(x, 0.0f) + __logf(1.0f + __expf(-fabsf(x)));
}
__device__ __forceinline__ uint32_t smem_u32(const void* p) {
    uint32_t a;
    asm("{ .reg .u64 t; cvta.to.shared.u64 t, %1; cvt.u32.u64 %0, t; }"
        : "=r"(a) : "l"(p));
    return a;
}
__device__ __forceinline__ uint32_t pkbf(float a, float b) {   // hi=a, lo=b
    uint32_t r; asm("cvt.rn.bf16x2.f32 %0, %1, %2;" : "=r"(r) : "f"(a), "f"(b));
    return r;
}
__device__ __forceinline__ void ldsm4(uint32_t* r, uint32_t addr) {
    asm volatile("ldmatrix.sync.aligned.m8n8.x4.shared.b16 {%0,%1,%2,%3}, [%4];"
                 : "=r"(r[0]), "=r"(r[1]), "=r"(r[2]), "=r"(r[3]) : "r"(addr));
}
__device__ __forceinline__ void mma_bf16(float* c, const uint32_t* a,
                                         uint32_t b0, uint32_t b1) {
    asm volatile(
        "mma.sync.aligned.m16n8k16.row.col.f32.bf16.bf16.f32 "
        "{%0,%1,%2,%3}, {%4,%5,%6,%7}, {%8,%9}, {%0,%1,%2,%3};"
        : "+f"(c[0]), "+f"(c[1]), "+f"(c[2]), "+f"(c[3])
        : "r"(a[0]), "r"(a[1]), "r"(a[2]), "r"(a[3]), "r"(b0), "r"(b1));
}

// ---- SMEM layout (bytes), per 128-thread CTA ----
// W1T: [192 n'][64 k] bf16, row stride 144B. n' 0..63: A-proj (W1 rows 64+k),
// 64..127: B-proj (rows 128+k), 128..191: core (rows k).
static constexpr int S_W1H = 0;        // 27648
static constexpr int S_W1L = 27648;    // 27648
static constexpr int S_CAB = 55296;    // float[8 rows][13 vecs][68] = 28288
static constexpr int S_B1  = 83584;    // float[64] = 256
static constexpr int S_H   = 83840;    // bf16 h: 4 warps x 32x144B = 18432
static constexpr int SMEM_BYTES = 102272;

__global__ void __launch_bounds__(128, 2) three_body_kernel(
    const float* __restrict__ core,   // [B, 64]
    const float* __restrict__ ligs,   // [B, 6, 64]
    const float* __restrict__ W1,     // [192, 64]
    const float* __restrict__ b1,     // [64]
    const float* __restrict__ W2,     // [64, 32]
    const float* __restrict__ b2,     // [32]
    const float* __restrict__ W3,     // [32]
    const float* __restrict__ b3,     // [1]
    float* __restrict__ out,          // [B]
    int B)
{
    extern __shared__ unsigned char sm[];
    float* s_cab = reinterpret_cast<float*>(sm + S_CAB);
    float* s_b1  = reinterpret_cast<float*>(sm + S_B1);

    const uint32_t smem_base = smem_u32(sm);
    const int tid  = threadIdx.x;
    const int lane = tid & 31;
    const int wid  = tid >> 5;

    // ---- stage W1^T hi/lo (bf16) ----
    for (int idx = tid; idx < 12288; idx += 128) {
        int n = idx >> 6, k = idx & 63;
        float w;
        if      (n < 64)  w = W1[(64  + k) * 64 + n];
        else if (n < 128) w = W1[(128 + k) * 64 + (n - 64)];
        else              w = W1[k * 64 + (n - 128)];
        __nv_bfloat16 h = __float2bfloat16(w);
        float res = w - __bfloat162float(h);
        *reinterpret_cast<__nv_bfloat16*>(sm + S_W1H + n * 144 + k * 2) = h;
        *reinterpret_cast<__nv_bfloat16*>(sm + S_W1L + n * 144 + k * 2) =
            __float2bfloat16(res);
    }
    if (tid < 64) s_b1[tid] = b1[tid];

    // ---- W2 fragments in registers: B1 = bf16(W2), B2 = residual ----
    uint32_t B1f[4][4][2], B2f[4][4][2];
    {
        const int krow = (lane & 3) * 2;
        const int ncol = lane >> 2;
        #pragma unroll
        for (int kt = 0; kt < 4; kt++) {
            #pragma unroll
            for (int nt = 0; nt < 4; nt++) {
                int k0 = kt * 16 + krow, n = nt * 8 + ncol;
                float w00 = W2[(k0 + 0) * 32 + n], w01 = W2[(k0 + 1) * 32 + n];
                float w08 = W2[(k0 + 8) * 32 + n], w09 = W2[(k0 + 9) * 32 + n];
                uint32_t h0 = pkbf(w01, w00);
                uint32_t h1 = pkbf(w09, w08);
                float r00 = w00 - __uint_as_float(h0 << 16);
                float r01 = w01 - __uint_as_float(h0 & 0xFFFF0000u);
                float r08 = w08 - __uint_as_float(h1 << 16);
                float r09 = w09 - __uint_as_float(h1 & 0xFFFF0000u);
                B1f[kt][nt][0] = h0;  B1f[kt][nt][1] = h1;
                B2f[kt][nt][0] = pkbf(r01, r00);
                B2f[kt][nt][1] = pkbf(r09, r08);
            }
        }
    }
    float b2v[8], w3v[8];
    #pragma unroll
    for (int nt = 0; nt < 4; nt++)
        #pragma unroll
        for (int e = 0; e < 2; e++) {
            int n = nt * 8 + (lane & 3) * 2 + e;
            b2v[nt * 2 + e] = b2[n];
            w3v[nt * 2 + e] = W3[n];
        }
    int pi, pj;
    if (lane < 30) { pi = lane / 5; int jj = lane % 5; pj = jj + (jj >= pi ? 1 : 0); }
    else           { pi = 0; pj = 1; }

    const float b3v = b3[0];
    const int   r0  = lane >> 2;          // fragment row within m16
    const int   c0  = (lane & 3) * 2;     // fragment col pair base

    const uint32_t hbase = smem_base + S_H + wid * 4608;
    char* hrow = (char*)sm + S_H + wid * 4608 + lane * 144;
    const uint32_t roff = (uint32_t)(lane & 15) * 144 + (uint32_t)(lane >> 4) * 16;
    const uint32_t bmat = smem_base + S_W1H + roff;   // ldsm base for W1T hi

    const int n_groups = B >> 3;   // 4096

    __syncthreads();

    for (int g = blockIdx.x; g < n_groups; g += gridDim.x) {
        const int rbase = g << 3;
        __syncthreads();   // previous group's phase-2 cab reads complete

        // ================= phase 1: layer-1 GEMMs =================
        if (wid < 3) {
            // ligand pair (2w, 2w+1) stacked as M=16 (rows 0-7 / 8-15)
            const int ka = 2 * wid, kb = 2 * wid + 1;
            const float* xa = ligs + (size_t)(rbase + r0) * 384 + ka * 64;
            const float* xb = ligs + (size_t)(rbase + r0) * 384 + kb * 64;
            uint32_t af[4][4];
            #pragma unroll
            for (int kt = 0; kt < 4; kt++) {
                int c = kt * 16 + c0;
                float2 x00 = *reinterpret_cast<const float2*>(xa + c);
                float2 x10 = *reinterpret_cast<const float2*>(xb + c);
                float2 x01 = *reinterpret_cast<const float2*>(xa + c + 8);
                float2 x11 = *reinterpret_cast<const float2*>(xb + c + 8);
                af[kt][0] = pkbf(x00.y, x00.x);  af[kt][1] = pkbf(x10.y, x10.x);
                af[kt][2] = pkbf(x01.y, x01.x);  af[kt][3] = pkbf(x11.y, x11.x);
            }
            #pragma unroll
            for (int np = 0; np < 8; np++) {
                float a0[4] = {0.f, 0.f, 0.f, 0.f}, a1[4] = {0.f, 0.f, 0.f, 0.f};
                #pragma unroll
                for (int kt = 0; kt < 4; kt++) {
                    uint32_t bh[4], bl[4];
                    uint32_t adr = bmat + (uint32_t)np * 2304 + (uint32_t)kt * 32;
                    ldsm4(bh, adr);
                    ldsm4(bl, adr + (S_W1L - S_W1H));
                    mma_bf16(a0, af[kt], bh[0], bh[2]);
                    mma_bf16(a0, af[kt], bl[0], bl[2]);
                    mma_bf16(a1, af[kt], bh[1], bh[3]);
                    mma_bf16(a1, af[kt], bl[1], bl[3]);
                }
                #pragma unroll
                for (int ntl = 0; ntl < 2; ntl++) {
                    const float* a = ntl ? a1 : a0;
                    int n = np * 16 + ntl * 8 + c0;
                    int d = n & 63;
                    int vecA = (n < 64) ? ka : 6 + ka;
                    int vecB = (n < 64) ? kb : 6 + kb;
                    *reinterpret_cast<float2*>(s_cab + (r0 * 13 + vecA) * 68 + d) =
                        make_float2(a[0], a[1]);
                    *reinterpret_cast<float2*>(s_cab + (r0 * 13 + vecB) * 68 + d) =
                        make_float2(a[2], a[3]);
                }
            }
        } else {
            // core projection (+b1): M=8 real rows (m-rows 8-15 discarded)
            const float* xc = core + (size_t)(rbase + r0) * 64;
            uint32_t af[4][4];
            #pragma unroll
            for (int kt = 0; kt < 4; kt++) {
                int c = kt * 16 + c0;
                float2 x00 = *reinterpret_cast<const float2*>(xc + c);
                float2 x01 = *reinterpret_cast<const float2*>(xc + c + 8);
                af[kt][0] = pkbf(x00.y, x00.x);  af[kt][1] = af[kt][0];
                af[kt][2] = pkbf(x01.y, x01.x);  af[kt][3] = af[kt][2];
            }
            #pragma unroll
            for (int np = 0; np < 4; np++) {
                float a0[4] = {0.f, 0.f, 0.f, 0.f}, a1[4] = {0.f, 0.f, 0.f, 0.f};
                #pragma unroll
                for (int kt = 0; kt < 4; kt++) {
                    uint32_t bh[4], bl[4];
                    uint32_t adr = bmat + (uint32_t)(128 + np * 16) * 144
                                 + (uint32_t)kt * 32;
                    ldsm4(bh, adr);
                    ldsm4(bl, adr + (S_W1L - S_W1H));
                    mma_bf16(a0, af[kt], bh[0], bh[2]);
                    mma_bf16(a0, af[kt], bl[0], bl[2]);
                    mma_bf16(a1, af[kt], bh[1], bh[3]);
                    mma_bf16(a1, af[kt], bl[1], bl[3]);
                }
                #pragma unroll
                for (int ntl = 0; ntl < 2; ntl++) {
                    const float* a = ntl ? a1 : a0;
                    int d = np * 16 + ntl * 8 + c0;   // n == d for core
                    *reinterpret_cast<float2*>(s_cab + (r0 * 13 + 12) * 68 + d) =
                        make_float2(a[0] + s_b1[d], a[1] + s_b1[d + 1]);
                }
            }
        }
        __syncthreads();   // cab complete

        // ================= phase 2: h-build + layer-2 GEMM, 2 rows =================
        #pragma unroll
        for (int rr = 0; rr < 2; rr++) {
            const int row = wid * 2 + rr;
            const float* vA = s_cab + (row * 13 + pi) * 68;
            const float* vB = s_cab + (row * 13 + 6 + pj) * 68;
            const float* vC = s_cab + (row * 13 + 12) * 68;

            uint32_t lor[32];   // h-lo kept in registers until hi GEMM done
            #pragma unroll
            for (int q2 = 0; q2 < 8; q2++) {
                uint32_t hb[4];
                #pragma unroll
                for (int h = 0; h < 2; h++) {
                    int q = q2 * 2 + h;
                    float4 a = *reinterpret_cast<const float4*>(vA + q * 4);
                    float4 b = *reinterpret_cast<const float4*>(vB + q * 4);
                    float4 c = *reinterpret_cast<const float4*>(vC + q * 4);
                    float h0 = softplus_f(a.x + b.x + c.x);
                    float h1 = softplus_f(a.y + b.y + c.y);
                    float h2 = softplus_f(a.z + b.z + c.z);
                    float h3 = softplus_f(a.w + b.w + c.w);
                    uint32_t p0 = pkbf(h1, h0);
                    uint32_t p1 = pkbf(h3, h2);
                    float l0 = h0 - __uint_as_float(p0 << 16);
                    float l1 = h1 - __uint_as_float(p0 & 0xFFFF0000u);
                    float l2 = h2 - __uint_as_float(p1 << 16);
                    float l3 = h3 - __uint_as_float(p1 & 0xFFFF0000u);
                    hb[h * 2] = p0;  hb[h * 2 + 1] = p1;
                    lor[q2 * 4 + h * 2]     = pkbf(l1, l0);
                    lor[q2 * 4 + h * 2 + 1] = pkbf(l3, l2);
                }
                *reinterpret_cast<uint4*>(hrow + q2 * 16) =
                    make_uint4(hb[0], hb[1], hb[2], hb[3]);
            }
            __syncwarp();

            float acc[2][4][4];
            #pragma unroll
            for (int mt = 0; mt < 2; mt++)
                #pragma unroll
                for (int nt = 0; nt < 4; nt++)
                    #pragma unroll
                    for (int e = 0; e < 4; e++) acc[mt][nt][e] = 0.0f;

            // hi products: hi*B1 + hi*B2
            #pragma unroll
            for (int mt = 0; mt < 2; mt++) {
                #pragma unroll
                for (int kt = 0; kt < 4; kt++) {
                    uint32_t afr[4];
                    ldsm4(afr, hbase + (uint32_t)mt * 2304 + roff + (uint32_t)kt * 32);
                    #pragma unroll
                    for (int nt = 0; nt < 4; nt++)
                        mma_bf16(acc[mt][nt], afr, B1f[kt][nt][0], B1f[kt][nt][1]);
                    #pragma unroll
                    for (int nt = 0; nt < 4; nt++)
                        mma_bf16(acc[mt][nt], afr, B2f[kt][nt][0], B2f[kt][nt][1]);
                }
            }
            __syncwarp();   // all hi ldsm complete; safe to overwrite buffer

            #pragma unroll
            for (int q2 = 0; q2 < 8; q2++)
                *reinterpret_cast<uint4*>(hrow + q2 * 16) =
                    make_uint4(lor[q2 * 4], lor[q2 * 4 + 1],
                               lor[q2 * 4 + 2], lor[q2 * 4 + 3]);
            __syncwarp();

            // lo product: lo*B1
            #pragma unroll
            for (int mt = 0; mt < 2; mt++) {
                #pragma unroll
                for (int kt = 0; kt < 4; kt++) {
                    uint32_t afr[4];
                    ldsm4(afr, hbase + (uint32_t)mt * 2304 + roff + (uint32_t)kt * 32);
                    #pragma unroll
                    for (int nt = 0; nt < 4; nt++)
                        mma_bf16(acc[mt][nt], afr, B1f[kt][nt][0], B1f[kt][nt][1]);
                }
            }

            // epilogue: y = softplus(t + b2) @ W3, mask dummies, reduce
            float total = 0.0f;
            #pragma unroll
            for (int mt = 0; mt < 2; mt++) {
                #pragma unroll
                for (int hf = 0; hf < 2; hf++) {
                    int prow = mt * 16 + (lane >> 2) + hf * 8;
                    float part = 0.0f;
                    #pragma unroll
                    for (int nt = 0; nt < 4; nt++)
                        #pragma unroll
                        for (int e = 0; e < 2; e++)
                            part += softplus_f(acc[mt][nt][hf * 2 + e] + b2v[nt * 2 + e])
                                    * w3v[nt * 2 + e];
                    if (prow < 30) total += part;
                }
            }
            #pragma unroll
            for (int off = 16; off; off >>= 1)
                total += __shfl_xor_sync(FULLMASK, total, off);
            if (lane == 0)
                out[rbase + row] = 0.5f * total + 15.0f * b3v;
            __syncwarp();   // h buffer free for next row
        }
    }
}

extern "C" void kernel_launch(void* const* d_in, const int* in_sizes, int n_in,
                              void* d_out, int out_size) {
    const float* core = (const float*)d_in[0];
    const float* ligs = (const float*)d_in[1];
    const float* W1   = (const float*)d_in[2];
    const float* b1   = (const float*)d_in[3];
    const float* W2   = (const float*)d_in[4];
    const float* b2   = (const float*)d_in[5];
    const float* W3   = (const float*)d_in[6];
    const float* b3   = (const float*)d_in[7];
    float* out = (float*)d_out;

    const int B = in_sizes[0] / 64;   // 32768

    cudaFuncSetAttribute(three_body_kernel,
                         cudaFuncAttributeMaxDynamicSharedMemorySize, SMEM_BYTES);

    // 296 CTAs = 2 per SM (SMEM-limited); grid-stride over 4096 groups.
    three_body_kernel<<<296, 128, SMEM_BYTES>>>(
        core, ligs, W1, b1, W2, b2, W3, b3, out, B);
}

// round 9
// speedup vs baseline: 2.2141x; 1.1302x over previous
#include <cuda_runtime.h>
#include <cuda_bf16.h>
#include <cstdint>

// ThreeBodyLayer — round 9: 12 warps/SM (192-thr CTAs x2/SM), 12-row groups.
// Register/SMEM diet: h-hi-only layer-2 product, W2-hi-only fragments,
// xor-swizzled 128B/256B SMEM rows (no pad). W1 stays bf16 hi+lo.
//
// Phase 1: warp k (0-5) = ligand k as M=16 (12 real rows + 4 clamped pads)
//   @ W1ab^T (n=128); warps 0-3 also take one n16 tile of core proj (+b1).
//   C -> cab[12 rows][13 vecs][64 f32] (256B rows, vec-chunk swizzle).
// Phase 2: warp w rows {2w, 2w+1}; lane p = ordered pair p: h = softplus(
//   cp + A_i + B_j) -> bf16 hi -> swizzled h buffer; 32 MMAs vs register
//   B1f; epilogue softplus(t+b2)@W3, dummy mask, shfl reduce.

#define FULLMASK 0xFFFFFFFFu

__device__ __forceinline__ float softplus_f(float x) {
    return fmaxf(x, 0.0f) + __logf(1.0f + __expf(-fabsf(x)));
}
__device__ __forceinline__ uint32_t smem_u32(const void* p) {
    uint32_t a;
    asm("{ .reg .u64 t; cvta.to.shared.u64 t, %1; cvt.u32.u64 %0, t; }"
        : "=r"(a) : "l"(p));
    return a;
}
__device__ __forceinline__ uint32_t pkbf(float a, float b) {   // hi=a, lo=b
    uint32_t r; asm("cvt.rn.bf16x2.f32 %0, %1, %2;" : "=r"(r) : "f"(a), "f"(b));
    return r;
}
__device__ __forceinline__ void ldsm4(uint32_t* r, uint32_t addr) {
    asm volatile("ldmatrix.sync.aligned.m8n8.x4.shared.b16 {%0,%1,%2,%3}, [%4];"
                 : "=r"(r[0]), "=r"(r[1]), "=r"(r[2]), "=r"(r[3]) : "r"(addr));
}
__device__ __forceinline__ void mma_bf16(float* c, const uint32_t* a,
                                         uint32_t b0, uint32_t b1) {
    asm volatile(
        "mma.sync.aligned.m16n8k16.row.col.f32.bf16.bf16.f32 "
        "{%0,%1,%2,%3}, {%4,%5,%6,%7}, {%8,%9}, {%0,%1,%2,%3};"
        : "+f"(c[0]), "+f"(c[1]), "+f"(c[2]), "+f"(c[3])
        : "r"(a[0]), "r"(a[1]), "r"(a[2]), "r"(a[3]), "r"(b0), "r"(b1));
}

// ---- SMEM layout (bytes) per 192-thread CTA ----
// W1T tables: [192 n'][64 k] bf16, 128B rows, chunk xor ((n&7)<<4).
//   n' 0..63: A-proj (W1 rows 64+k), 64..127: B-proj (128+k), 128..191: core (k).
// cab: [12 rows][13 vecs][64 f32], 256B vec-rows, chunk xor ((vec&7)<<4).
// h:   [6 warps][32 pair-rows][64 bf16], 128B rows, chunk xor ((p&7)<<4).
static constexpr int S_W1H = 0;        // 24576
static constexpr int S_W1L = 24576;    // 24576
static constexpr int S_CAB = 49152;    // 12*13*256 = 39936
static constexpr int S_H   = 89088;    // 6*4096    = 24576
static constexpr int SMEM_BYTES = 113664;

static constexpr int ROWS_PER_GROUP = 12;

__global__ void __launch_bounds__(192, 2) three_body_kernel(
    const float* __restrict__ core,   // [B, 64]
    const float* __restrict__ ligs,   // [B, 6, 64]
    const float* __restrict__ W1,     // [192, 64]
    const float* __restrict__ b1,     // [64]
    const float* __restrict__ W2,     // [64, 32]
    const float* __restrict__ b2,     // [32]
    const float* __restrict__ W3,     // [32]
    const float* __restrict__ b3,     // [1]
    float* __restrict__ out,          // [B]
    int B)
{
    extern __shared__ unsigned char sm[];
    const uint32_t smem_base = smem_u32(sm);
    const int tid  = threadIdx.x;
    const int lane = tid & 31;
    const int wid  = tid >> 5;        // 0..5

    // ---- stage W1^T hi/lo (bf16, swizzled 128B rows) ----
    for (int idx = tid; idx < 12288; idx += 192) {
        int n = idx >> 6, k = idx & 63;
        float w;
        if      (n < 64)  w = W1[(64  + k) * 64 + n];
        else if (n < 128) w = W1[(128 + k) * 64 + (n - 64)];
        else              w = W1[k * 64 + (n - 128)];
        __nv_bfloat16 h = __float2bfloat16(w);
        float res = w - __bfloat162float(h);
        int byte = n * 128 + ((2 * k) ^ ((n & 7) << 4));
        *reinterpret_cast<__nv_bfloat16*>(sm + S_W1H + byte) = h;
        *reinterpret_cast<__nv_bfloat16*>(sm + S_W1L + byte) = __float2bfloat16(res);
    }

    // ---- W2 fragments in registers (hi only) ----
    uint32_t B1f[4][4][2];
    {
        const int krow = (lane & 3) * 2;
        const int ncol = lane >> 2;
        #pragma unroll
        for (int kt = 0; kt < 4; kt++)
            #pragma unroll
            for (int nt = 0; nt < 4; nt++) {
                int k0 = kt * 16 + krow, n = nt * 8 + ncol;
                B1f[kt][nt][0] = pkbf(W2[(k0 + 1) * 32 + n], W2[(k0 + 0) * 32 + n]);
                B1f[kt][nt][1] = pkbf(W2[(k0 + 9) * 32 + n], W2[(k0 + 8) * 32 + n]);
            }
    }
    float b2v[8], w3v[8];
    #pragma unroll
    for (int nt = 0; nt < 4; nt++)
        #pragma unroll
        for (int e = 0; e < 2; e++) {
            int n = nt * 8 + (lane & 3) * 2 + e;
            b2v[nt * 2 + e] = b2[n];
            w3v[nt * 2 + e] = W3[n];
        }
    int pi, pj;
    if (lane < 30) { pi = lane / 5; int jj = lane % 5; pj = jj + (jj >= pi ? 1 : 0); }
    else           { pi = 0; pj = 1; }

    const float b3v = b3[0];
    const int r0  = lane >> 2;            // fragment row in m16 (0..7)
    const int c0  = (lane & 3) * 2;       // fragment col pair base
    const uint32_t lsw  = (uint32_t)(lane & 7) << 4;       // ldsm row swizzle
    const uint32_t csel = (uint32_t)(lane >> 4) * 16;      // 16B sub-chunk
    const uint32_t w1row = (uint32_t)(lane & 15) * 128;
    const uint32_t w1baseH = smem_base + S_W1H;
    const uint32_t hbl  = smem_base + S_H + wid * 4096;
    char* hrow = (char*)sm + S_H + wid * 4096 + lane * 128;
    const uint32_t hsw = (uint32_t)(lane & 7) << 4;

    const int n_groups = (B + ROWS_PER_GROUP - 1) / ROWS_PER_GROUP;   // 2731

    __syncthreads();

    for (int g = blockIdx.x; g < n_groups; g += gridDim.x) {
        const int rbase = g * ROWS_PER_GROUP;
        __syncthreads();   // previous group's phase-2 cab reads complete

        // ================= phase 1: layer-1 GEMMs =================
        {
            // ligand k = wid, M=16 tile (rows 0..11 real, 12..15 pad/clamped)
            const int k  = wid;
            const int ra = rbase + r0;                         // always < B
            const int rb8 = rbase + r0 + 8;
            const int rb = (rb8 < B) ? rb8 : (B - 1);
            const float* xa = ligs + (size_t)ra * 384 + k * 64;
            const float* xb = ligs + (size_t)rb * 384 + k * 64;
            uint32_t af[4][4];
            #pragma unroll
            for (int kt = 0; kt < 4; kt++) {
                int c = kt * 16 + c0;
                float2 x00 = *reinterpret_cast<const float2*>(xa + c);
                float2 x10 = *reinterpret_cast<const float2*>(xb + c);
                float2 x01 = *reinterpret_cast<const float2*>(xa + c + 8);
                float2 x11 = *reinterpret_cast<const float2*>(xb + c + 8);
                af[kt][0] = pkbf(x00.y, x00.x);  af[kt][1] = pkbf(x10.y, x10.x);
                af[kt][2] = pkbf(x01.y, x01.x);  af[kt][3] = pkbf(x11.y, x11.x);
            }
            #pragma unroll
            for (int np = 0; np < 8; np++) {
                float a0[4] = {0.f, 0.f, 0.f, 0.f}, a1[4] = {0.f, 0.f, 0.f, 0.f};
                #pragma unroll
                for (int kt = 0; kt < 4; kt++) {
                    uint32_t bh[4], bl[4];
                    uint32_t adr = w1baseH + (uint32_t)np * 2048 + w1row
                                 + (((uint32_t)kt * 32 + csel) ^ lsw);
                    ldsm4(bh, adr);
                    ldsm4(bl, adr + (S_W1L - S_W1H));
                    mma_bf16(a0, af[kt], bh[0], bh[2]);
                    mma_bf16(a0, af[kt], bl[0], bl[2]);
                    mma_bf16(a1, af[kt], bh[1], bh[3]);
                    mma_bf16(a1, af[kt], bl[1], bl[3]);
                }
                #pragma unroll
                for (int ntl = 0; ntl < 2; ntl++) {
                    const float* a = ntl ? a1 : a0;
                    int n = np * 16 + ntl * 8 + c0;
                    int d = n & 63;
                    int vec = (n < 64) ? k : 6 + k;
                    uint32_t sb = (uint32_t)(d * 4) ^ ((uint32_t)(vec & 7) << 4);
                    char* base = (char*)sm + S_CAB + vec * 256 + sb;
                    *reinterpret_cast<float2*>(base + r0 * 3328) =
                        make_float2(a[0], a[1]);
                    if (r0 < 4)
                        *reinterpret_cast<float2*>(base + (r0 + 8) * 3328) =
                            make_float2(a[2], a[3]);
                }
            }
        }
        if (wid < 4) {
            // core projection (+b1): warp wid owns n-tile np = wid (n = d)
            const int np = wid;
            const int ra = rbase + r0;
            const int rb8 = rbase + r0 + 8;
            const int rb = (rb8 < B) ? rb8 : (B - 1);
            const float* xa = core + (size_t)ra * 64;
            const float* xb = core + (size_t)rb * 64;
            uint32_t af[4][4];
            #pragma unroll
            for (int kt = 0; kt < 4; kt++) {
                int c = kt * 16 + c0;
                float2 x00 = *reinterpret_cast<const float2*>(xa + c);
                float2 x10 = *reinterpret_cast<const float2*>(xb + c);
                float2 x01 = *reinterpret_cast<const float2*>(xa + c + 8);
                float2 x11 = *reinterpret_cast<const float2*>(xb + c + 8);
                af[kt][0] = pkbf(x00.y, x00.x);  af[kt][1] = pkbf(x10.y, x10.x);
                af[kt][2] = pkbf(x01.y, x01.x);  af[kt][3] = pkbf(x11.y, x11.x);
            }
            float a0[4] = {0.f, 0.f, 0.f, 0.f}, a1[4] = {0.f, 0.f, 0.f, 0.f};
            #pragma unroll
            for (int kt = 0; kt < 4; kt++) {
                uint32_t bh[4], bl[4];
                uint32_t adr = w1baseH + (uint32_t)(128 + np * 16) * 128 + w1row
                             + (((uint32_t)kt * 32 + csel) ^ lsw);
                ldsm4(bh, adr);
                ldsm4(bl, adr + (S_W1L - S_W1H));
                mma_bf16(a0, af[kt], bh[0], bh[2]);
                mma_bf16(a0, af[kt], bl[0], bl[2]);
                mma_bf16(a1, af[kt], bh[1], bh[3]);
                mma_bf16(a1, af[kt], bl[1], bl[3]);
            }
            #pragma unroll
            for (int ntl = 0; ntl < 2; ntl++) {
                const float* a = ntl ? a1 : a0;
                int d = np * 16 + ntl * 8 + c0;           // n == d for core
                float bb0 = __ldg(b1 + d), bb1 = __ldg(b1 + d + 1);
                uint32_t sb = (uint32_t)(d * 4) ^ 64u;    // vec 12: (12&7)<<4 = 64
                char* base = (char*)sm + S_CAB + 12 * 256 + sb;
                *reinterpret_cast<float2*>(base + r0 * 3328) =
                    make_float2(a[0] + bb0, a[1] + bb1);
                if (r0 < 4)
                    *reinterpret_cast<float2*>(base + (r0 + 8) * 3328) =
                        make_float2(a[2] + bb0, a[3] + bb1);
            }
        }
        __syncthreads();   // cab complete

        // ================= phase 2: h-build + layer-2 GEMM, 2 rows =================
        #pragma unroll
        for (int rr = 0; rr < 2; rr++) {
            const int row = wid * 2 + rr;
            const char* rowb = (char*)sm + S_CAB + row * 3328;
            const char* baseA = rowb + pi * 256;
            const char* baseB = rowb + (6 + pj) * 256;
            const char* baseC = rowb + 12 * 256;
            const uint32_t vswA = (uint32_t)(pi & 7) << 4;
            const uint32_t vswB = (uint32_t)((6 + pj) & 7) << 4;

            #pragma unroll
            for (int q2 = 0; q2 < 8; q2++) {
                uint32_t hb[4];
                #pragma unroll
                for (int h = 0; h < 2; h++) {
                    uint32_t qb = (uint32_t)(q2 * 2 + h) * 16;
                    float4 a = *reinterpret_cast<const float4*>(baseA + (qb ^ vswA));
                    float4 b = *reinterpret_cast<const float4*>(baseB + (qb ^ vswB));
                    float4 c = *reinterpret_cast<const float4*>(baseC + (qb ^ 64u));
                    float h0 = softplus_f(a.x + b.x + c.x);
                    float h1 = softplus_f(a.y + b.y + c.y);
                    float h2 = softplus_f(a.z + b.z + c.z);
                    float h3 = softplus_f(a.w + b.w + c.w);
                    hb[h * 2]     = pkbf(h1, h0);
                    hb[h * 2 + 1] = pkbf(h3, h2);
                }
                *reinterpret_cast<uint4*>(hrow + (((uint32_t)q2 * 16) ^ hsw)) =
                    make_uint4(hb[0], hb[1], hb[2], hb[3]);
            }
            __syncwarp();

            float acc[2][4][4];
            #pragma unroll
            for (int mt = 0; mt < 2; mt++)
                #pragma unroll
                for (int nt = 0; nt < 4; nt++)
                    #pragma unroll
                    for (int e = 0; e < 4; e++) acc[mt][nt][e] = 0.0f;

            #pragma unroll
            for (int mt = 0; mt < 2; mt++)
                #pragma unroll
                for (int kt = 0; kt < 4; kt++) {
                    uint32_t afr[4];
                    uint32_t adr = hbl + (uint32_t)mt * 2048 + w1row
                                 + (((uint32_t)kt * 32 + csel) ^ lsw);
                    ldsm4(afr, adr);
                    #pragma unroll
                    for (int nt = 0; nt < 4; nt++)
                        mma_bf16(acc[mt][nt], afr, B1f[kt][nt][0], B1f[kt][nt][1]);
                }

            // epilogue: y = softplus(t + b2) @ W3, mask dummies, reduce
            float total = 0.0f;
            #pragma unroll
            for (int mt = 0; mt < 2; mt++)
                #pragma unroll
                for (int hf = 0; hf < 2; hf++) {
                    int prow = mt * 16 + (lane >> 2) + hf * 8;
                    float part = 0.0f;
                    #pragma unroll
                    for (int nt = 0; nt < 4; nt++)
                        #pragma unroll
                        for (int e = 0; e < 2; e++)
                            part += softplus_f(acc[mt][nt][hf * 2 + e] + b2v[nt * 2 + e])
                                    * w3v[nt * 2 + e];
                    if (prow < 30) total += part;
                }
            #pragma unroll
            for (int off = 16; off; off >>= 1)
                total += __shfl_xor_sync(FULLMASK, total, off);
            const int gr = rbase + row;
            if (lane == 0 && gr < B)
                out[gr] = 0.5f * total + 15.0f * b3v;
        }
    }
}

extern "C" void kernel_launch(void* const* d_in, const int* in_sizes, int n_in,
                              void* d_out, int out_size) {
    const float* core = (const float*)d_in[0];
    const float* ligs = (const float*)d_in[1];
    const float* W1   = (const float*)d_in[2];
    const float* b1   = (const float*)d_in[3];
    const float* W2   = (const float*)d_in[4];
    const float* b2   = (const float*)d_in[5];
    const float* W3   = (const float*)d_in[6];
    const float* b3   = (const float*)d_in[7];
    float* out = (float*)d_out;

    const int B = in_sizes[0] / 64;   // 32768

    cudaFuncSetAttribute(three_body_kernel,
                         cudaFuncAttributeMaxDynamicSharedMemorySize, SMEM_BYTES);

    // 296 CTAs = 2 per SM (113.7KB SMEM each); grid-stride over 2731 groups.
    three_body_kernel<<<296, 192, SMEM_BYTES>>>(
        core, ligs, W1, b1, W2, b2, W3, b3, out, B);
}